// round 14
// baseline (speedup 1.0000x reference)
#include <cuda_runtime.h>
#include <cuda_bf16.h>
#include <math.h>
#include <stdint.h>

#define NN      10000
#define NE      160000
#define ET      170000
#define IN_DIM  256
#define HID     128
#define HEADS   8
#define F1      1024
#define ODIM    64

#define K1E     (3 * IN_DIM)   // 768
#define K1A     (2 * IN_DIM)   // 512
#define K2E     (3 * F1)       // 3072
#define K2A     (2 * F1)       // 2048
#define SMX     96
#define CAP     128            // bucket capacity per dst

// ================= scratch =================
__device__ float g_xl1  [NN * F1];
__device__ float g_asrc1[NN * HEADS];
__device__ float g_adst1[NN * HEADS];
__device__ float g_h2   [NN * ODIM];
__device__ float g_asrc2[NN];
__device__ float g_adst2[NN];
__device__ int g_cursor[NN];
__device__ int g_csrsrc[NN * CAP];
__device__ __nv_bfloat16 g_xe  [NN * K1A];     // [hi | lo]
__device__ __nv_bfloat16 g_w1e [F1 * K1E];     // [hi | lo | hi]
__device__ __nv_bfloat16 g_h1e [NN * K2A];     // [hi | lo]
__device__ __nv_bfloat16 g_w2e [ODIM * K2E];   // [hi | lo | hi]

__device__ __forceinline__ uint32_t smem_u32(const void* p) {
    uint32_t a;
    asm("{ .reg .u64 t; cvta.to.shared.u64 t, %1; cvt.u32.u64 %0, t; }" : "=r"(a) : "l"(p));
    return a;
}
__device__ __forceinline__ void ldmatrix_x4(uint32_t* r, uint32_t addr) {
    asm volatile("ldmatrix.sync.aligned.m8n8.x4.shared.b16 {%0,%1,%2,%3}, [%4];"
        : "=r"(r[0]), "=r"(r[1]), "=r"(r[2]), "=r"(r[3]) : "r"(addr));
}
__device__ __forceinline__ void cp16(uint32_t dst, const void* src, int bytes) {
    asm volatile("cp.async.cg.shared.global [%0], [%1], 16, %2;"
        :: "r"(dst), "l"(src), "r"(bytes));
}
#define CP_COMMIT() asm volatile("cp.async.commit_group;" ::: "memory")
#define CP_WAIT(n)  asm volatile("cp.async.wait_group %0;" :: "n"(n) : "memory")

// ================= side0: zero cursor + cvt_w2 =================
__global__ void k_side0(const float* __restrict__ W2) {
    int i = blockIdx.x * blockDim.x + threadIdx.x;
    if (i < NN) g_cursor[i] = 0;
    int j = i - NN;
    if (j >= 0 && j < F1 * ODIM) {
        int k = j >> 6, n = j & (ODIM - 1);
        float v = W2[j];
        __nv_bfloat16 hi = __float2bfloat16(v);
        __nv_bfloat16 lo = __float2bfloat16(v - __bfloat162float(hi));
        __nv_bfloat16* row = g_w2e + (size_t)n * K2E;
        row[k] = hi; row[k + F1] = lo; row[k + 2 * F1] = hi;
    }
}

// ================= bucket scatter =================
__global__ void k_scatter(const int* __restrict__ ei) {
    int e = blockIdx.x * blockDim.x + threadIdx.x;
    if (e >= ET) return;
    int s, d;
    if (e < NE) { s = ei[e]; d = ei[NE + e]; }
    else        { s = e - NE; d = e - NE; }
    int pos = atomicAdd(&g_cursor[d], 1);
    g_csrsrc[d * CAP + pos] = s;
}

// ================= conversions (split for stream overlap) =================
__global__ void k_cvt_x(const float* __restrict__ x) {
    int i = blockIdx.x * blockDim.x + threadIdx.x;
    if (i >= NN * IN_DIM) return;
    float v = x[i];
    __nv_bfloat16 hi = __float2bfloat16(v);
    __nv_bfloat16 lo = __float2bfloat16(v - __bfloat162float(hi));
    int r = i >> 8, k = i & (IN_DIM - 1);
    __nv_bfloat16* row = g_xe + (size_t)r * K1A;
    row[k] = hi; row[k + IN_DIM] = lo;
}
__global__ void k_cvt_w1(const float* __restrict__ W1) {
    int j = blockIdx.x * blockDim.x + threadIdx.x;
    if (j >= IN_DIM * F1) return;
    int k = j >> 10, n = j & (F1 - 1);
    float v = W1[j];
    __nv_bfloat16 hi = __float2bfloat16(v);
    __nv_bfloat16 lo = __float2bfloat16(v - __bfloat162float(hi));
    __nv_bfloat16* row = g_w1e + (size_t)n * K1E;
    row[k] = hi; row[k + IN_DIM] = lo; row[k + 2 * IN_DIM] = hi;
}

// ================= cp.async-pipelined bf16 mma GEMM, paired-stage loop =====
__device__ __forceinline__ void mma16816(float* c, const uint32_t* a, const uint32_t* b) {
    asm volatile(
        "mma.sync.aligned.m16n8k16.row.col.f32.bf16.bf16.f32 "
        "{%0,%1,%2,%3}, {%4,%5,%6,%7}, {%8,%9}, {%0,%1,%2,%3};"
        : "+f"(c[0]), "+f"(c[1]), "+f"(c[2]), "+f"(c[3])
        : "r"(a[0]), "r"(a[1]), "r"(a[2]), "r"(a[3]), "r"(b[0]), "r"(b[1]));
}

template<int BM, int BN, int STAGES>
constexpr int gemm_smem_bytes() { return STAGES * (BM + BN) * 40 * 2; }

template<int BM, int BN, int WM, int WN, int FOLD, int STAGES>
__global__ void __launch_bounds__(256) k_mma_gemm(
        const __nv_bfloat16* __restrict__ A,
        const __nv_bfloat16* __restrict__ B,
        float* __restrict__ C, int M, int N, int K, int n_off,
        const float* __restrict__ att_src, const float* __restrict__ att_dst,
        float* __restrict__ out_s, float* __restrict__ out_d, int nh) {
    constexpr int WT_M = BM / WM;
    constexpr int WT_N = BN / WN;
    constexpr int MF = WT_M / 16;
    constexpr int NF = WT_N / 8;
    constexpr int LDS = 40;
    constexpr int A_LD = BM * 4 / 256;
    constexpr int B_LD = (BN * 4 + 255) / 256;
    constexpr uint32_t ABUF = BM * LDS * 2;
    constexpr uint32_t BBUF = BN * LDS * 2;
    constexpr int PREF = 3;                 // with STAGES=5, pair scheme

    extern __shared__ char dynsm[];
    __nv_bfloat16* Asm = (__nv_bfloat16*)dynsm;
    __nv_bfloat16* Bsm = Asm + STAGES * BM * LDS;

    int tid = threadIdx.x;
    int w = tid >> 5, lane = tid & 31;
    int g = lane >> 2, t4 = lane & 3;
    int wm = w / WN, wn = w % WN;
    int m0 = blockIdx.y * BM;
    int n0 = blockIdx.x * BN + n_off;
    int wrow = wm * WT_M, wcol = wn * WT_N;
    const int lda = 2 * FOLD;
    const int NIT = K / 32;                 // even for both GEMMs

    int arow = lane & 15;
    int akof = (lane >> 4) << 3;
    int q8 = lane >> 3;
    int brow = ((q8 & 2) ? 8 : 0) + (lane & 7);
    int bkof = (q8 & 1) << 3;
    uint32_t aS = smem_u32(Asm);
    uint32_t bS = smem_u32(Bsm);

    float acc[MF][NF][4];
    #pragma unroll
    for (int i = 0; i < MF; i++)
        #pragma unroll
        for (int j = 0; j < NF; j++)
            #pragma unroll
            for (int q = 0; q < 4; q++) acc[i][j][q] = 0.f;

    auto issue_tile = [&](int it) {
        if (it < NIT) {
            int k0 = it * 32;
            int k0a = (k0 >= FOLD) ? k0 - FOLD : k0;
            int st = it % STAGES;
            #pragma unroll
            for (int q = 0; q < A_LD; q++) {
                int idx = tid + q * 256;
                int row = idx >> 2, seg = idx & 3;
                int gr = m0 + row;
                int grc = gr < M ? gr : M - 1;
                cp16(aS + st * ABUF + 2u * (row * LDS + seg * 8),
                     A + (size_t)grc * lda + k0a + seg * 8, gr < M ? 16 : 0);
            }
            #pragma unroll
            for (int q = 0; q < B_LD; q++) {
                int idx = tid + q * 256;
                if (BN * 4 % 256 == 0 || idx < BN * 4) {
                    int row = idx >> 2, seg = idx & 3;
                    cp16(bS + st * BBUF + 2u * (row * LDS + seg * 8),
                         B + (size_t)(n0 + row) * K + k0 + seg * 8, 16);
                }
            }
        }
        CP_COMMIT();
    };

    auto compute_stage = [&](int st) {
        uint32_t aB = aS + st * ABUF;
        uint32_t bB = bS + st * BBUF;
        #pragma unroll
        for (int ks = 0; ks < 32; ks += 16) {
            uint32_t af[MF][4], bf[NF][2];
            #pragma unroll
            for (int mi = 0; mi < MF; mi++)
                ldmatrix_x4(af[mi], aB + 2u * ((wrow + mi * 16 + arow) * LDS + ks + akof));
            #pragma unroll
            for (int nj = 0; nj < NF / 2; nj++) {
                uint32_t tt[4];
                ldmatrix_x4(tt, bB + 2u * ((wcol + nj * 16 + brow) * LDS + ks + bkof));
                bf[2 * nj][0] = tt[0]; bf[2 * nj][1] = tt[1];
                bf[2 * nj + 1][0] = tt[2]; bf[2 * nj + 1][1] = tt[3];
            }
            #pragma unroll
            for (int mi = 0; mi < MF; mi++)
                #pragma unroll
                for (int ni = 0; ni < NF; ni++)
                    mma16816(acc[mi][ni], af[mi], bf[ni]);
        }
    };

    #pragma unroll
    for (int p = 0; p < PREF; p++) issue_tile(p);

    for (int it = 0; it < NIT; it += 2) {
        CP_WAIT(PREF - 2);                  // tiles it, it+1 complete
        __syncthreads();
        compute_stage(it % STAGES);
        compute_stage((it + 1) % STAGES);
        issue_tile(it + PREF);
        issue_tile(it + PREF + 1);
    }
    CP_WAIT(0);
    __syncthreads();

    // ---- fused attention-coefficient epilogue ----
    if (att_src) {
        float* s1a = (float*)Asm;
        float* s2a = s1a + BM;
        if (tid < BM) { s1a[tid] = 0.f; s2a[tid] = 0.f; }
        __syncthreads();
        float asr[NF][2], adr[NF][2];
        #pragma unroll
        for (int ni = 0; ni < NF; ni++)
            #pragma unroll
            for (int q = 0; q < 2; q++) {
                int gc = n0 + wcol + ni * 8 + 2 * t4 + q;
                asr[ni][q] = att_src[gc];
                adr[ni][q] = att_dst[gc];
            }
        #pragma unroll
        for (int mi = 0; mi < MF; mi++) {
            #pragma unroll
            for (int half = 0; half < 2; half++) {
                float p1 = 0.f, p2 = 0.f;
                #pragma unroll
                for (int ni = 0; ni < NF; ni++)
                    #pragma unroll
                    for (int q = 0; q < 2; q++) {
                        float v = acc[mi][ni][half * 2 + q];
                        p1 += v * asr[ni][q];
                        p2 += v * adr[ni][q];
                    }
                p1 += __shfl_xor_sync(~0u, p1, 1); p1 += __shfl_xor_sync(~0u, p1, 2);
                p2 += __shfl_xor_sync(~0u, p2, 1); p2 += __shfl_xor_sync(~0u, p2, 2);
                if (t4 == 0) {
                    int r = wrow + mi * 16 + half * 8 + g;
                    atomicAdd(&s1a[r], p1);
                    atomicAdd(&s2a[r], p2);
                }
            }
        }
        __syncthreads();
        int head = n0 / (N / nh);
        if (tid < BM && m0 + tid < M) {
            out_s[(size_t)(m0 + tid) * nh + head] = s1a[tid];
            out_d[(size_t)(m0 + tid) * nh + head] = s2a[tid];
        }
    }

    // ---- C store ----
    #pragma unroll
    for (int mi = 0; mi < MF; mi++) {
        #pragma unroll
        for (int ni = 0; ni < NF; ni++) {
            int r = m0 + wrow + mi * 16 + g;
            int c = n0 + wcol + ni * 8 + 2 * t4;
            if (r < M)     *(float2*)&C[(size_t)r * N + c]       = make_float2(acc[mi][ni][0], acc[mi][ni][1]);
            if (r + 8 < M) *(float2*)&C[(size_t)(r + 8) * N + c] = make_float2(acc[mi][ni][2], acc[mi][ni][3]);
        }
    }
}

// ===== fused layer-1 softmax + agg + bias + ELU for 4 heads [h0, h0+4) =====
__global__ void __launch_bounds__(128) k_smagg1(const float* __restrict__ b1, int h0) {
    int d = blockIdx.x;
    int t = threadIdx.x, lane = t & 31, w = t >> 5;
    int jb = d * CAP;
    int je = jb + g_cursor[d];
    __shared__ float s_m[4], s_rd[4];
    __shared__ float sv[SMX * 4];
    __shared__ int   ssrc[32];
    __shared__ float salpha[32 * 4];

    int gh = h0 + w;
    float adst = g_adst1[d * HEADS + gh];
    float m = -1e30f;
    for (int j = jb + lane; j < je; j += 32) {
        int s = g_csrsrc[j];
        float v = g_asrc1[s * HEADS + gh] + adst;
        v = v > 0.f ? v : 0.2f * v;
        int idx = j - jb;
        if (idx < SMX) sv[idx * 4 + w] = v;
        m = fmaxf(m, v);
    }
    #pragma unroll
    for (int o = 16; o; o >>= 1) m = fmaxf(m, __shfl_xor_sync(~0u, m, o));
    float den = 0.f;
    for (int j = jb + lane; j < je; j += 32) {
        int idx = j - jb;
        float v;
        if (idx < SMX) v = sv[idx * 4 + w];
        else {
            v = g_asrc1[g_csrsrc[j] * HEADS + gh] + adst;
            v = v > 0.f ? v : 0.2f * v;
        }
        float e = expf(v - m);
        if (idx < SMX) sv[idx * 4 + w] = e;
        den += e;
    }
    #pragma unroll
    for (int o = 16; o; o >>= 1) den += __shfl_xor_sync(~0u, den, o);
    if (lane == 0) { s_m[w] = m; s_rd[w] = 1.f / (den + 1e-16f); }
    __syncthreads();

    int e4 = t >> 2, h4 = t & 3;
    float rd2 = s_rd[h4], m2 = s_m[h4];
    float adst4 = g_adst1[d * HEADS + h0 + h4];
    int lh = t >> 5;
    int fc = h0 * 32 + t;
    const float4* xl = (const float4*)g_xl1;
    float4 acc = make_float4(0.f, 0.f, 0.f, 0.f);

    for (int j0 = jb; j0 < je; j0 += 32) {
        int cnt = min(32, je - j0);
        __syncthreads();
        if (t < cnt) ssrc[t] = g_csrsrc[j0 + t];
        __syncthreads();
        if (e4 < cnt) {
            int idx = j0 - jb + e4;
            float e;
            if (idx < SMX) e = sv[idx * 4 + h4];
            else {
                float v = g_asrc1[ssrc[e4] * HEADS + h0 + h4] + adst4;
                v = v > 0.f ? v : 0.2f * v;
                e = expf(v - m2);
            }
            salpha[e4 * 4 + h4] = e * rd2;
        }
        __syncthreads();
        #pragma unroll 2
        for (int jj = 0; jj < cnt; jj++) {
            int s = ssrc[jj];
            float a = salpha[jj * 4 + lh];
            float4 xv = xl[(size_t)s * (F1 / 4) + fc];
            acc.x += a * xv.x; acc.y += a * xv.y;
            acc.z += a * xv.z; acc.w += a * xv.w;
        }
    }

    float4 bb = ((const float4*)b1)[fc];
    float v[4];
    v[0] = acc.x + bb.x; v[1] = acc.y + bb.y; v[2] = acc.z + bb.z; v[3] = acc.w + bb.w;
    #pragma unroll
    for (int q = 0; q < 4; q++) v[q] = v[q] > 0.f ? v[q] : expm1f(v[q]);
    __nv_bfloat16 hi[4], lo[4];
    #pragma unroll
    for (int q = 0; q < 4; q++) {
        hi[q] = __float2bfloat16(v[q]);
        lo[q] = __float2bfloat16(v[q] - __bfloat162float(hi[q]));
    }
    __nv_bfloat16* row = g_h1e + (size_t)d * K2A;
    *(uint2*)&row[4 * fc]      = *(uint2*)hi;
    *(uint2*)&row[4 * fc + F1] = *(uint2*)lo;
}

// ===== fused layer-2 softmax + aggregation + bias + LayerNorm =====
__global__ void __launch_bounds__(64) k_smagg2ln(
        const float* __restrict__ b2, const float* __restrict__ gamma,
        const float* __restrict__ beta, float* __restrict__ out) {
    int d = blockIdx.x;
    int t = threadIdx.x, lane = t & 31, w = t >> 5;
    int jb = d * CAP;
    int je = jb + g_cursor[d];
    __shared__ float redm[2], redd[2];
    __shared__ int   ssrc[64];
    __shared__ float salpha[64];

    float adst = g_adst2[d];
    float m = -1e30f;
    for (int j = jb + t; j < je; j += 64) {
        float v = g_asrc2[g_csrsrc[j]] + adst;
        v = v > 0.f ? v : 0.2f * v;
        m = fmaxf(m, v);
    }
    #pragma unroll
    for (int o = 16; o; o >>= 1) m = fmaxf(m, __shfl_xor_sync(~0u, m, o));
    if (lane == 0) redm[w] = m;
    __syncthreads();
    m = fmaxf(redm[0], redm[1]);
    float den = 0.f;
    for (int j = jb + t; j < je; j += 64) {
        float v = g_asrc2[g_csrsrc[j]] + adst;
        v = v > 0.f ? v : 0.2f * v;
        den += expf(v - m);
    }
    #pragma unroll
    for (int o = 16; o; o >>= 1) den += __shfl_xor_sync(~0u, den, o);
    if (lane == 0) redd[w] = den;
    __syncthreads();
    float rd = 1.f / (redd[0] + redd[1] + 1e-16f);

    float acc = 0.f;
    for (int j0 = jb; j0 < je; j0 += 64) {
        int cnt = min(64, je - j0);
        __syncthreads();
        if (t < cnt) {
            int s = g_csrsrc[j0 + t];
            ssrc[t] = s;
            float v = g_asrc2[s] + adst;
            v = v > 0.f ? v : 0.2f * v;
            salpha[t] = expf(v - m) * rd;
        }
        __syncthreads();
        #pragma unroll 2
        for (int jj = 0; jj < cnt; jj++)
            acc += salpha[jj] * g_h2[(size_t)ssrc[jj] * ODIM + t];
    }

    float val = acc + b2[t];
    float s = val;
    #pragma unroll
    for (int o = 16; o; o >>= 1) s += __shfl_xor_sync(~0u, s, o);
    __syncthreads();
    if (lane == 0) redd[w] = s;
    __syncthreads();
    float mu = (redd[0] + redd[1]) * (1.f / 64.f);
    float dv = val - mu;
    float q = dv * dv;
    #pragma unroll
    for (int o = 16; o; o >>= 1) q += __shfl_xor_sync(~0u, q, o);
    __syncthreads();
    if (lane == 0) redm[w] = q;
    __syncthreads();
    float inv = rsqrtf((redm[0] + redm[1]) * (1.f / 64.f) + 1e-5f);
    out[(size_t)d * ODIM + t] = dv * inv * gamma[t] + beta[t];
}

// ================= launch =================
extern "C" void kernel_launch(void* const* d_in, const int* in_sizes, int n_in,
                              void* d_out, int out_size) {
    const float* x     = (const float*)d_in[0];
    const int*   ei    = (const int*)  d_in[1];
    const float* W1    = (const float*)d_in[2];
    const float* as1   = (const float*)d_in[3];
    const float* ad1   = (const float*)d_in[4];
    const float* b1    = (const float*)d_in[5];
    const float* W2    = (const float*)d_in[6];
    const float* as2   = (const float*)d_in[7];
    const float* ad2   = (const float*)d_in[8];
    const float* b2    = (const float*)d_in[9];
    const float* gamma = (const float*)d_in[10];
    const float* beta  = (const float*)d_in[11];
    float* out = (float*)d_out;

    __nv_bfloat16 *xe, *w1e, *h1e, *w2e;
    float *xl1, *h2, *asrc1, *adst1, *asrc2, *adst2;
    cudaGetSymbolAddress((void**)&xe,    g_xe);
    cudaGetSymbolAddress((void**)&w1e,   g_w1e);
    cudaGetSymbolAddress((void**)&h1e,   g_h1e);
    cudaGetSymbolAddress((void**)&w2e,   g_w2e);
    cudaGetSymbolAddress((void**)&xl1,   g_xl1);
    cudaGetSymbolAddress((void**)&h2,    g_h2);
    cudaGetSymbolAddress((void**)&asrc1, g_asrc1);
    cudaGetSymbolAddress((void**)&adst1, g_adst1);
    cudaGetSymbolAddress((void**)&asrc2, g_asrc2);
    cudaGetSymbolAddress((void**)&adst2, g_adst2);

    constexpr int SM1 = gemm_smem_bytes<128, 128, 5>();   // 102400
    constexpr int SM2 = gemm_smem_bytes<64, 64, 5>();     // 51200
    cudaFuncSetAttribute(k_mma_gemm<128, 128, 2, 4, IN_DIM, 5>,
                         cudaFuncAttributeMaxDynamicSharedMemorySize, SM1);
    cudaFuncSetAttribute(k_mma_gemm<64, 64, 2, 4, F1, 5>,
                         cudaFuncAttributeMaxDynamicSharedMemorySize, SM2);

    static cudaStream_t s_side = nullptr;
    static cudaEvent_t  s_ev0 = nullptr, s_evW1 = nullptr, s_evA = nullptr,
                        s_evScat = nullptr, s_ev1 = nullptr;
    if (!s_side) {
        cudaStreamCreateWithFlags(&s_side, cudaStreamNonBlocking);
        cudaEventCreateWithFlags(&s_ev0,   cudaEventDisableTiming);
        cudaEventCreateWithFlags(&s_evW1,  cudaEventDisableTiming);
        cudaEventCreateWithFlags(&s_evA,   cudaEventDisableTiming);
        cudaEventCreateWithFlags(&s_evScat,cudaEventDisableTiming);
        cudaEventCreateWithFlags(&s_ev1,   cudaEventDisableTiming);
    }

    cudaEventRecord(s_ev0, 0);
    cudaStreamWaitEvent(s_side, s_ev0, 0);

    // submission order: cvt_x(0), cvt_w1(1), side0(2), GEMM1a(3 -> ncu target)
    k_cvt_x<<<(NN * IN_DIM + 255) / 256, 256>>>(x);
    k_cvt_w1<<<(IN_DIM * F1 + 255) / 256, 256, 0, s_side>>>(W1);
    cudaEventRecord(s_evW1, s_side);
    k_side0<<<(NN + F1 * ODIM + 255) / 256, 256, 0, s_side>>>(W2);
    cudaStreamWaitEvent(0, s_evW1, 0);
    {   // GEMM1 first half: heads 0-3 (cols 0-511)
        dim3 g(4, (NN + 127) / 128);
        k_mma_gemm<128, 128, 2, 4, IN_DIM, 5><<<g, 256, SM1>>>(
            xe, w1e, xl1, NN, F1, K1E, 0, as1, ad1, asrc1, adst1, HEADS);
    }
    k_scatter<<<(ET + 255) / 256, 256, 0, s_side>>>(ei);
    cudaEventRecord(s_evScat, s_side);
    cudaEventRecord(s_evA, 0);

    // side stream: smagg1 heads 0-3 (after scatter on-stream + GEMM1a via evA)
    cudaStreamWaitEvent(s_side, s_evA, 0);
    k_smagg1<<<NN, 128, 0, s_side>>>(b1, 0);
    cudaEventRecord(s_ev1, s_side);

    {   // GEMM1 second half: heads 4-7 (cols 512-1023), overlaps smagg1a
        dim3 g(4, (NN + 127) / 128);
        k_mma_gemm<128, 128, 2, 4, IN_DIM, 5><<<g, 256, SM1>>>(
            xe, w1e, xl1, NN, F1, K1E, 512, as1, ad1, asrc1, adst1, HEADS);
    }
    cudaStreamWaitEvent(0, s_evScat, 0);
    k_smagg1<<<NN, 128>>>(b1, 4);

    cudaStreamWaitEvent(0, s_ev1, 0);
    {   // GEMM2 + fused attn2
        dim3 g(1, (NN + 63) / 64);
        k_mma_gemm<64, 64, 2, 4, F1, 5><<<g, 256, SM2>>>(
            h1e, w2e, h2, NN, ODIM, K2E, 0, as2, ad2, asrc2, adst2, 1);
    }
    k_smagg2ln<<<NN, 64>>>(b2, gamma, beta, out);
}

// round 15
// speedup vs baseline: 1.0980x; 1.0980x over previous
#include <cuda_runtime.h>
#include <cuda_bf16.h>
#include <math.h>
#include <stdint.h>

#define NN      10000
#define NE      160000
#define ET      170000
#define IN_DIM  256
#define HID     128
#define HEADS   8
#define F1      1024
#define ODIM    64

#define K1E     (3 * IN_DIM)   // 768
#define K1A     (2 * IN_DIM)   // 512
#define K2E     (3 * F1)       // 3072
#define K2A     (2 * F1)       // 2048
#define SMX     96
#define CAP     128            // bucket capacity per dst

// ================= scratch =================
__device__ float g_xl1  [NN * F1];
__device__ float g_asrc1[NN * HEADS];
__device__ float g_adst1[NN * HEADS];
__device__ float g_h2   [NN * ODIM];
__device__ float g_asrc2[NN];
__device__ float g_adst2[NN];
__device__ int g_cursor[NN];
__device__ int g_csrsrc[NN * CAP];
__device__ __nv_bfloat16 g_xe  [NN * K1A];     // [hi | lo]
__device__ __nv_bfloat16 g_w1e [F1 * K1E];     // [hi | lo | hi]
__device__ __nv_bfloat16 g_h1e [NN * K2A];     // [hi | lo]
__device__ __nv_bfloat16 g_w2e [ODIM * K2E];   // [hi | lo | hi]

__device__ __forceinline__ uint32_t smem_u32(const void* p) {
    uint32_t a;
    asm("{ .reg .u64 t; cvta.to.shared.u64 t, %1; cvt.u32.u64 %0, t; }" : "=r"(a) : "l"(p));
    return a;
}
__device__ __forceinline__ void ldmatrix_x4(uint32_t* r, uint32_t addr) {
    asm volatile("ldmatrix.sync.aligned.m8n8.x4.shared.b16 {%0,%1,%2,%3}, [%4];"
        : "=r"(r[0]), "=r"(r[1]), "=r"(r[2]), "=r"(r[3]) : "r"(addr));
}
__device__ __forceinline__ void cp16(uint32_t dst, const void* src, int bytes) {
    asm volatile("cp.async.cg.shared.global [%0], [%1], 16, %2;"
        :: "r"(dst), "l"(src), "r"(bytes));
}
#define CP_COMMIT() asm volatile("cp.async.commit_group;" ::: "memory")
#define CP_WAIT(n)  asm volatile("cp.async.wait_group %0;" :: "n"(n) : "memory")

// ================= side0: zero cursor + cvt_w2 =================
__global__ void k_side0(const float* __restrict__ W2) {
    int i = blockIdx.x * blockDim.x + threadIdx.x;
    if (i < NN) g_cursor[i] = 0;
    int j = i - NN;
    if (j >= 0 && j < F1 * ODIM) {
        int k = j >> 6, n = j & (ODIM - 1);
        float v = W2[j];
        __nv_bfloat16 hi = __float2bfloat16(v);
        __nv_bfloat16 lo = __float2bfloat16(v - __bfloat162float(hi));
        __nv_bfloat16* row = g_w2e + (size_t)n * K2E;
        row[k] = hi; row[k + F1] = lo; row[k + 2 * F1] = hi;
    }
}

// ================= bucket scatter =================
__global__ void k_scatter(const int* __restrict__ ei) {
    int e = blockIdx.x * blockDim.x + threadIdx.x;
    if (e >= ET) return;
    int s, d;
    if (e < NE) { s = ei[e]; d = ei[NE + e]; }
    else        { s = e - NE; d = e - NE; }
    int pos = atomicAdd(&g_cursor[d], 1);
    g_csrsrc[d * CAP + pos] = s;
}

// ================= conversions =================
__global__ void k_cvt1(const float* __restrict__ x, const float* __restrict__ W1) {
    int i = blockIdx.x * blockDim.x + threadIdx.x;
    if (i < NN * IN_DIM) {
        float v = x[i];
        __nv_bfloat16 hi = __float2bfloat16(v);
        __nv_bfloat16 lo = __float2bfloat16(v - __bfloat162float(hi));
        int r = i >> 8, k = i & (IN_DIM - 1);
        __nv_bfloat16* row = g_xe + (size_t)r * K1A;
        row[k] = hi; row[k + IN_DIM] = lo;
        return;
    }
    int j = i - NN * IN_DIM;
    if (j < IN_DIM * F1) {
        int k = j >> 10, n = j & (F1 - 1);
        float v = W1[j];
        __nv_bfloat16 hi = __float2bfloat16(v);
        __nv_bfloat16 lo = __float2bfloat16(v - __bfloat162float(hi));
        __nv_bfloat16* row = g_w1e + (size_t)n * K1E;
        row[k] = hi; row[k + IN_DIM] = lo; row[k + 2 * IN_DIM] = hi;
    }
}

// ================= cp.async-pipelined bf16 mma GEMM (dynamic smem) =================
__device__ __forceinline__ void mma16816(float* c, const uint32_t* a, const uint32_t* b) {
    asm volatile(
        "mma.sync.aligned.m16n8k16.row.col.f32.bf16.bf16.f32 "
        "{%0,%1,%2,%3}, {%4,%5,%6,%7}, {%8,%9}, {%0,%1,%2,%3};"
        : "+f"(c[0]), "+f"(c[1]), "+f"(c[2]), "+f"(c[3])
        : "r"(a[0]), "r"(a[1]), "r"(a[2]), "r"(a[3]), "r"(b[0]), "r"(b[1]));
}

template<int BM, int BN, int STAGES>
constexpr int gemm_smem_bytes() { return STAGES * (BM + BN) * 40 * 2; }

template<int BM, int BN, int WM, int WN, int FOLD, int STAGES>
__global__ void __launch_bounds__(256) k_mma_gemm(
        const __nv_bfloat16* __restrict__ A,
        const __nv_bfloat16* __restrict__ B,
        float* __restrict__ C, int M, int N, int K, int n_off,
        const float* __restrict__ att_src, const float* __restrict__ att_dst,
        float* __restrict__ out_s, float* __restrict__ out_d, int nh) {
    constexpr int WT_M = BM / WM;
    constexpr int WT_N = BN / WN;
    constexpr int MF = WT_M / 16;
    constexpr int NF = WT_N / 8;
    constexpr int LDS = 40;
    constexpr int A_LD = BM * 4 / 256;
    constexpr int B_LD = (BN * 4 + 255) / 256;
    constexpr uint32_t ABUF = BM * LDS * 2;
    constexpr uint32_t BBUF = BN * LDS * 2;
    constexpr int PREF = STAGES - 1;

    extern __shared__ char dynsm[];
    __nv_bfloat16* Asm = (__nv_bfloat16*)dynsm;
    __nv_bfloat16* Bsm = Asm + STAGES * BM * LDS;

    int tid = threadIdx.x;
    int w = tid >> 5, lane = tid & 31;
    int g = lane >> 2, t4 = lane & 3;
    int wm = w / WN, wn = w % WN;
    int m0 = blockIdx.y * BM;
    int n0 = blockIdx.x * BN + n_off;
    int wrow = wm * WT_M, wcol = wn * WT_N;
    const int lda = 2 * FOLD;
    const int NIT = K / 32;

    int arow = lane & 15;
    int akof = (lane >> 4) << 3;
    int q8 = lane >> 3;
    int brow = ((q8 & 2) ? 8 : 0) + (lane & 7);
    int bkof = (q8 & 1) << 3;
    uint32_t aS = smem_u32(Asm);
    uint32_t bS = smem_u32(Bsm);

    float acc[MF][NF][4];
    #pragma unroll
    for (int i = 0; i < MF; i++)
        #pragma unroll
        for (int j = 0; j < NF; j++)
            #pragma unroll
            for (int q = 0; q < 4; q++) acc[i][j][q] = 0.f;

    auto issue_tile = [&](int it) {
        if (it < NIT) {
            int k0 = it * 32;
            int k0a = (k0 >= FOLD) ? k0 - FOLD : k0;
            int st = it % STAGES;
            #pragma unroll
            for (int q = 0; q < A_LD; q++) {
                int idx = tid + q * 256;
                int row = idx >> 2, seg = idx & 3;
                int gr = m0 + row;
                int grc = gr < M ? gr : M - 1;
                cp16(aS + st * ABUF + 2u * (row * LDS + seg * 8),
                     A + (size_t)grc * lda + k0a + seg * 8, gr < M ? 16 : 0);
            }
            #pragma unroll
            for (int q = 0; q < B_LD; q++) {
                int idx = tid + q * 256;
                if (BN * 4 % 256 == 0 || idx < BN * 4) {
                    int row = idx >> 2, seg = idx & 3;
                    cp16(bS + st * BBUF + 2u * (row * LDS + seg * 8),
                         B + (size_t)(n0 + row) * K + k0 + seg * 8, 16);
                }
            }
        }
        CP_COMMIT();
    };

    #pragma unroll
    for (int p = 0; p < PREF; p++) issue_tile(p);

    for (int it = 0; it < NIT; it++) {
        CP_WAIT(PREF - 1);
        __syncthreads();
        int st = it % STAGES;
        uint32_t aB = aS + st * ABUF;
        uint32_t bB = bS + st * BBUF;
        #pragma unroll
        for (int ks = 0; ks < 32; ks += 16) {
            uint32_t af[MF][4], bf[NF][2];
            #pragma unroll
            for (int mi = 0; mi < MF; mi++)
                ldmatrix_x4(af[mi], aB + 2u * ((wrow + mi * 16 + arow) * LDS + ks + akof));
            #pragma unroll
            for (int nj = 0; nj < NF / 2; nj++) {
                uint32_t tt[4];
                ldmatrix_x4(tt, bB + 2u * ((wcol + nj * 16 + brow) * LDS + ks + bkof));
                bf[2 * nj][0] = tt[0]; bf[2 * nj][1] = tt[1];
                bf[2 * nj + 1][0] = tt[2]; bf[2 * nj + 1][1] = tt[3];
            }
            #pragma unroll
            for (int mi = 0; mi < MF; mi++)
                #pragma unroll
                for (int ni = 0; ni < NF; ni++)
                    mma16816(acc[mi][ni], af[mi], bf[ni]);
        }
        issue_tile(it + PREF);
    }
    CP_WAIT(0);
    __syncthreads();

    // ---- fused attention-coefficient epilogue (single writer per head) ----
    if (att_src) {
        float* s1a = (float*)Asm;
        float* s2a = s1a + BM;
        if (tid < BM) { s1a[tid] = 0.f; s2a[tid] = 0.f; }
        __syncthreads();
        float asr[NF][2], adr[NF][2];
        #pragma unroll
        for (int ni = 0; ni < NF; ni++)
            #pragma unroll
            for (int q = 0; q < 2; q++) {
                int gc = n0 + wcol + ni * 8 + 2 * t4 + q;
                asr[ni][q] = att_src[gc];
                adr[ni][q] = att_dst[gc];
            }
        #pragma unroll
        for (int mi = 0; mi < MF; mi++) {
            #pragma unroll
            for (int half = 0; half < 2; half++) {
                float p1 = 0.f, p2 = 0.f;
                #pragma unroll
                for (int ni = 0; ni < NF; ni++)
                    #pragma unroll
                    for (int q = 0; q < 2; q++) {
                        float v = acc[mi][ni][half * 2 + q];
                        p1 += v * asr[ni][q];
                        p2 += v * adr[ni][q];
                    }
                p1 += __shfl_xor_sync(~0u, p1, 1); p1 += __shfl_xor_sync(~0u, p1, 2);
                p2 += __shfl_xor_sync(~0u, p2, 1); p2 += __shfl_xor_sync(~0u, p2, 2);
                if (t4 == 0) {
                    int r = wrow + mi * 16 + half * 8 + g;
                    atomicAdd(&s1a[r], p1);
                    atomicAdd(&s2a[r], p2);
                }
            }
        }
        __syncthreads();
        int head = n0 / (N / nh);
        if (tid < BM && m0 + tid < M) {
            out_s[(size_t)(m0 + tid) * nh + head] = s1a[tid];
            out_d[(size_t)(m0 + tid) * nh + head] = s2a[tid];
        }
    }

    // ---- C store ----
    #pragma unroll
    for (int mi = 0; mi < MF; mi++) {
        #pragma unroll
        for (int ni = 0; ni < NF; ni++) {
            int r = m0 + wrow + mi * 16 + g;
            int c = n0 + wcol + ni * 8 + 2 * t4;
            if (r < M)     *(float2*)&C[(size_t)r * N + c]       = make_float2(acc[mi][ni][0], acc[mi][ni][1]);
            if (r + 8 < M) *(float2*)&C[(size_t)(r + 8) * N + c] = make_float2(acc[mi][ni][2], acc[mi][ni][3]);
        }
    }
}

// ===== fused layer-1 softmax + agg + bias + ELU for nh heads [h0, h0+nh) =====
// block per dst, blockDim = 32*nh (warp w = head h0+w in phase 1).
__global__ void k_smagg1(const float* __restrict__ b1, int h0, int nh) {
    int d = blockIdx.x;
    int t = threadIdx.x, lane = t & 31, w = t >> 5;
    int jb = d * CAP;
    int je = jb + g_cursor[d];
    __shared__ float s_m[8], s_rd[8];
    __shared__ float sv[SMX * 8];
    __shared__ int   ssrc[32];
    __shared__ float salpha[32 * 8];

    int gh = h0 + w;
    float adst = g_adst1[d * HEADS + gh];
    float m = -1e30f;
    for (int j = jb + lane; j < je; j += 32) {
        int s = g_csrsrc[j];
        float v = g_asrc1[s * HEADS + gh] + adst;
        v = v > 0.f ? v : 0.2f * v;
        int idx = j - jb;
        if (idx < SMX) sv[idx * nh + w] = v;
        m = fmaxf(m, v);
    }
    #pragma unroll
    for (int o = 16; o; o >>= 1) m = fmaxf(m, __shfl_xor_sync(~0u, m, o));
    float den = 0.f;
    for (int j = jb + lane; j < je; j += 32) {
        int idx = j - jb;
        float v;
        if (idx < SMX) v = sv[idx * nh + w];
        else {
            v = g_asrc1[g_csrsrc[j] * HEADS + gh] + adst;
            v = v > 0.f ? v : 0.2f * v;
        }
        float e = expf(v - m);
        if (idx < SMX) sv[idx * nh + w] = e;
        den += e;
    }
    #pragma unroll
    for (int o = 16; o; o >>= 1) den += __shfl_xor_sync(~0u, den, o);
    if (lane == 0) { s_m[w] = m; s_rd[w] = 1.f / (den + 1e-16f); }
    __syncthreads();

    int eh = t / nh, hh = t % nh;         // alpha mapping: 32 edges x nh heads
    float rd2 = s_rd[hh], m2 = s_m[hh];
    float adsth = g_adst1[d * HEADS + h0 + hh];
    int lh = t >> 5;                       // channel-group local head
    int fc = h0 * 32 + t;                  // global float4 column
    const float4* xl = (const float4*)g_xl1;
    float4 acc = make_float4(0.f, 0.f, 0.f, 0.f);

    for (int j0 = jb; j0 < je; j0 += 32) {
        int cnt = min(32, je - j0);
        __syncthreads();
        if (t < cnt) ssrc[t] = g_csrsrc[j0 + t];
        __syncthreads();
        if (eh < cnt) {
            int idx = j0 - jb + eh;
            float e;
            if (idx < SMX) e = sv[idx * nh + hh];
            else {
                float v = g_asrc1[ssrc[eh] * HEADS + h0 + hh] + adsth;
                v = v > 0.f ? v : 0.2f * v;
                e = expf(v - m2);
            }
            salpha[eh * nh + hh] = e * rd2;
        }
        __syncthreads();
        #pragma unroll 2
        for (int jj = 0; jj < cnt; jj++) {
            int s = ssrc[jj];
            float a = salpha[jj * nh + lh];
            float4 xv = xl[(size_t)s * (F1 / 4) + fc];
            acc.x += a * xv.x; acc.y += a * xv.y;
            acc.z += a * xv.z; acc.w += a * xv.w;
        }
    }

    float4 bb = ((const float4*)b1)[fc];
    float v[4];
    v[0] = acc.x + bb.x; v[1] = acc.y + bb.y; v[2] = acc.z + bb.z; v[3] = acc.w + bb.w;
    #pragma unroll
    for (int q = 0; q < 4; q++) v[q] = v[q] > 0.f ? v[q] : expm1f(v[q]);
    __nv_bfloat16 hi[4], lo[4];
    #pragma unroll
    for (int q = 0; q < 4; q++) {
        hi[q] = __float2bfloat16(v[q]);
        lo[q] = __float2bfloat16(v[q] - __bfloat162float(hi[q]));
    }
    __nv_bfloat16* row = g_h1e + (size_t)d * K2A;
    *(uint2*)&row[4 * fc]      = *(uint2*)hi;
    *(uint2*)&row[4 * fc + F1] = *(uint2*)lo;
}

// ===== fused layer-2 softmax + aggregation + bias + LayerNorm =====
__global__ void __launch_bounds__(64) k_smagg2ln(
        const float* __restrict__ b2, const float* __restrict__ gamma,
        const float* __restrict__ beta, float* __restrict__ out) {
    int d = blockIdx.x;
    int t = threadIdx.x, lane = t & 31, w = t >> 5;
    int jb = d * CAP;
    int je = jb + g_cursor[d];
    __shared__ float redm[2], redd[2];
    __shared__ int   ssrc[64];
    __shared__ float salpha[64];

    float adst = g_adst2[d];
    float m = -1e30f;
    for (int j = jb + t; j < je; j += 64) {
        float v = g_asrc2[g_csrsrc[j]] + adst;
        v = v > 0.f ? v : 0.2f * v;
        m = fmaxf(m, v);
    }
    #pragma unroll
    for (int o = 16; o; o >>= 1) m = fmaxf(m, __shfl_xor_sync(~0u, m, o));
    if (lane == 0) redm[w] = m;
    __syncthreads();
    m = fmaxf(redm[0], redm[1]);
    float den = 0.f;
    for (int j = jb + t; j < je; j += 64) {
        float v = g_asrc2[g_csrsrc[j]] + adst;
        v = v > 0.f ? v : 0.2f * v;
        den += expf(v - m);
    }
    #pragma unroll
    for (int o = 16; o; o >>= 1) den += __shfl_xor_sync(~0u, den, o);
    if (lane == 0) redd[w] = den;
    __syncthreads();
    float rd = 1.f / (redd[0] + redd[1] + 1e-16f);

    float acc = 0.f;
    for (int j0 = jb; j0 < je; j0 += 64) {
        int cnt = min(64, je - j0);
        __syncthreads();
        if (t < cnt) {
            int s = g_csrsrc[j0 + t];
            ssrc[t] = s;
            float v = g_asrc2[s] + adst;
            v = v > 0.f ? v : 0.2f * v;
            salpha[t] = expf(v - m) * rd;
        }
        __syncthreads();
        #pragma unroll 2
        for (int jj = 0; jj < cnt; jj++)
            acc += salpha[jj] * g_h2[(size_t)ssrc[jj] * ODIM + t];
    }

    float val = acc + b2[t];
    float s = val;
    #pragma unroll
    for (int o = 16; o; o >>= 1) s += __shfl_xor_sync(~0u, s, o);
    __syncthreads();
    if (lane == 0) redd[w] = s;
    __syncthreads();
    float mu = (redd[0] + redd[1]) * (1.f / 64.f);
    float dv = val - mu;
    float q = dv * dv;
    #pragma unroll
    for (int o = 16; o; o >>= 1) q += __shfl_xor_sync(~0u, q, o);
    __syncthreads();
    if (lane == 0) redm[w] = q;
    __syncthreads();
    float inv = rsqrtf((redm[0] + redm[1]) * (1.f / 64.f) + 1e-5f);
    out[(size_t)d * ODIM + t] = dv * inv * gamma[t] + beta[t];
}

// ================= launch =================
extern "C" void kernel_launch(void* const* d_in, const int* in_sizes, int n_in,
                              void* d_out, int out_size) {
    const float* x     = (const float*)d_in[0];
    const int*   ei    = (const int*)  d_in[1];
    const float* W1    = (const float*)d_in[2];
    const float* as1   = (const float*)d_in[3];
    const float* ad1   = (const float*)d_in[4];
    const float* b1    = (const float*)d_in[5];
    const float* W2    = (const float*)d_in[6];
    const float* as2   = (const float*)d_in[7];
    const float* ad2   = (const float*)d_in[8];
    const float* b2    = (const float*)d_in[9];
    const float* gamma = (const float*)d_in[10];
    const float* beta  = (const float*)d_in[11];
    float* out = (float*)d_out;

    __nv_bfloat16 *xe, *w1e, *h1e, *w2e;
    float *xl1, *h2, *asrc1, *adst1, *asrc2, *adst2;
    cudaGetSymbolAddress((void**)&xe,    g_xe);
    cudaGetSymbolAddress((void**)&w1e,   g_w1e);
    cudaGetSymbolAddress((void**)&h1e,   g_h1e);
    cudaGetSymbolAddress((void**)&w2e,   g_w2e);
    cudaGetSymbolAddress((void**)&xl1,   g_xl1);
    cudaGetSymbolAddress((void**)&h2,    g_h2);
    cudaGetSymbolAddress((void**)&asrc1, g_asrc1);
    cudaGetSymbolAddress((void**)&adst1, g_adst1);
    cudaGetSymbolAddress((void**)&asrc2, g_asrc2);
    cudaGetSymbolAddress((void**)&adst2, g_adst2);

    constexpr int SM1 = gemm_smem_bytes<128, 128, 4>();   // 81920
    constexpr int SM2 = gemm_smem_bytes<64, 64, 6>();     // 61440
    cudaFuncSetAttribute(k_mma_gemm<128, 128, 2, 4, IN_DIM, 4>,
                         cudaFuncAttributeMaxDynamicSharedMemorySize, SM1);
    cudaFuncSetAttribute(k_mma_gemm<64, 64, 2, 4, F1, 6>,
                         cudaFuncAttributeMaxDynamicSharedMemorySize, SM2);

    static cudaStream_t s_side = nullptr;
    static cudaEvent_t  s_ev0 = nullptr, s_evA = nullptr, s_evScat = nullptr, s_ev1 = nullptr;
    if (!s_side) {
        cudaStreamCreateWithFlags(&s_side, cudaStreamNonBlocking);
        cudaEventCreateWithFlags(&s_ev0,   cudaEventDisableTiming);
        cudaEventCreateWithFlags(&s_evA,   cudaEventDisableTiming);
        cudaEventCreateWithFlags(&s_evScat,cudaEventDisableTiming);
        cudaEventCreateWithFlags(&s_ev1,   cudaEventDisableTiming);
    }

    cudaEventRecord(s_ev0, 0);
    cudaStreamWaitEvent(s_side, s_ev0, 0);

    // submission order: cvt1(0), side0(1), scatter(2), GEMM1a(3 -> ncu target)
    k_cvt1<<<(NN * IN_DIM + IN_DIM * F1 + 255) / 256, 256>>>(x, W1);
    k_side0<<<(NN + F1 * ODIM + 255) / 256, 256, 0, s_side>>>(W2);
    k_scatter<<<(ET + 255) / 256, 256, 0, s_side>>>(ei);
    {   // GEMM1a: heads 0-1 (cols 0-255), 158 CTAs ~ 1 wave
        dim3 g(2, (NN + 127) / 128);
        k_mma_gemm<128, 128, 2, 4, IN_DIM, 4><<<g, 256, SM1>>>(
            xe, w1e, xl1, NN, F1, K1E, 0, as1, ad1, asrc1, adst1, HEADS);
    }
    cudaEventRecord(s_evScat, s_side);
    cudaEventRecord(s_evA, 0);

    // side stream: smagg1 heads 0-1, overlaps GEMM1b
    cudaStreamWaitEvent(s_side, s_evA, 0);
    k_smagg1<<<NN, 64, 0, s_side>>>(b1, 0, 2);
    cudaEventRecord(s_ev1, s_side);

    {   // GEMM1b: heads 2-7 (cols 256-1023), 474 CTAs ~ 2 waves
        dim3 g(6, (NN + 127) / 128);
        k_mma_gemm<128, 128, 2, 4, IN_DIM, 4><<<g, 256, SM1>>>(
            xe, w1e, xl1, NN, F1, K1E, 256, as1, ad1, asrc1, adst1, HEADS);
    }
    cudaStreamWaitEvent(0, s_evScat, 0);
    k_smagg1<<<NN, 192>>>(b1, 2, 6);

    cudaStreamWaitEvent(0, s_ev1, 0);
    {   // GEMM2 + fused attn2
        dim3 g(1, (NN + 63) / 64);
        k_mma_gemm<64, 64, 2, 4, F1, 6><<<g, 256, SM2>>>(
            h1e, w2e, h2, NN, ODIM, K2E, 0, as2, ad2, asrc2, adst2, 1);
    }
    k_smagg2ln<<<NN, 64>>>(b2, gamma, beta, out);
}

// round 16
// speedup vs baseline: 1.3332x; 1.2142x over previous
#include <cuda_runtime.h>
#include <cuda_fp16.h>
#include <math.h>
#include <stdint.h>

#define NN      10000
#define NE      160000
#define ET      170000
#define IN_DIM  256
#define HID     128
#define HEADS   8
#define F1      1024
#define ODIM    64

#define K1      (2 * IN_DIM)   // 512  : GEMM1 K (A=[hi|lo], B=[hi|hi])
#define K2      (2 * F1)       // 2048 : GEMM2 K
#define SMX     96
#define CAP     128            // bucket capacity per dst

// ================= scratch =================
__device__ float g_xl1  [NN * F1];
__device__ float g_asrc1[NN * HEADS];
__device__ float g_adst1[NN * HEADS];
__device__ float g_h2   [NN * ODIM];
__device__ float g_asrc2[NN];
__device__ float g_adst2[NN];
__device__ int g_cursor[NN];
__device__ int g_csrsrc[NN * CAP];
__device__ __half g_xe  [NN * K1];      // [hi | lo]
__device__ __half g_w1e [F1 * K1];      // [hi | hi]
__device__ __half g_h1e [NN * K2];      // [hi | lo]
__device__ __half g_w2e [ODIM * K2];    // [hi | hi]

__device__ __forceinline__ uint32_t smem_u32(const void* p) {
    uint32_t a;
    asm("{ .reg .u64 t; cvta.to.shared.u64 t, %1; cvt.u32.u64 %0, t; }" : "=r"(a) : "l"(p));
    return a;
}
__device__ __forceinline__ void ldmatrix_x4(uint32_t* r, uint32_t addr) {
    asm volatile("ldmatrix.sync.aligned.m8n8.x4.shared.b16 {%0,%1,%2,%3}, [%4];"
        : "=r"(r[0]), "=r"(r[1]), "=r"(r[2]), "=r"(r[3]) : "r"(addr));
}
__device__ __forceinline__ void cp16(uint32_t dst, const void* src, int bytes) {
    asm volatile("cp.async.cg.shared.global [%0], [%1], 16, %2;"
        :: "r"(dst), "l"(src), "r"(bytes));
}
#define CP_COMMIT() asm volatile("cp.async.commit_group;" ::: "memory")
#define CP_WAIT(n)  asm volatile("cp.async.wait_group %0;" :: "n"(n) : "memory")

// ================= side0: zero cursor + cvt_w2 ([hi|hi]) =================
__global__ void k_side0(const float* __restrict__ W2) {
    int i = blockIdx.x * blockDim.x + threadIdx.x;
    if (i < NN) g_cursor[i] = 0;
    int j = i - NN;
    if (j >= 0 && j < F1 * ODIM) {
        int k = j >> 6, n = j & (ODIM - 1);
        __half hi = __float2half(W2[j]);
        __half* row = g_w2e + (size_t)n * K2;
        row[k] = hi; row[k + F1] = hi;
    }
}

// ================= bucket scatter =================
__global__ void k_scatter(const int* __restrict__ ei) {
    int e = blockIdx.x * blockDim.x + threadIdx.x;
    if (e >= ET) return;
    int s, d;
    if (e < NE) { s = ei[e]; d = ei[NE + e]; }
    else        { s = e - NE; d = e - NE; }
    int pos = atomicAdd(&g_cursor[d], 1);
    g_csrsrc[d * CAP + pos] = s;
}

// ================= cvt: x -> [hi|lo], W1 -> [hi|hi] =================
__global__ void k_cvt1(const float* __restrict__ x, const float* __restrict__ W1) {
    int i = blockIdx.x * blockDim.x + threadIdx.x;
    if (i < NN * IN_DIM) {
        float v = x[i];
        __half hi = __float2half(v);
        __half lo = __float2half(v - __half2float(hi));
        int r = i >> 8, k = i & (IN_DIM - 1);
        __half* row = g_xe + (size_t)r * K1;
        row[k] = hi; row[k + IN_DIM] = lo;
        return;
    }
    int j = i - NN * IN_DIM;
    if (j < IN_DIM * F1) {
        int k = j >> 10, n = j & (F1 - 1);
        __half hi = __float2half(W1[j]);
        __half* row = g_w1e + (size_t)n * K1;
        row[k] = hi; row[k + IN_DIM] = hi;
    }
}

// ================= cp.async-pipelined fp16 mma GEMM (dynamic smem) =================
__device__ __forceinline__ void mma16816(float* c, const uint32_t* a, const uint32_t* b) {
    asm volatile(
        "mma.sync.aligned.m16n8k16.row.col.f32.f16.f16.f32 "
        "{%0,%1,%2,%3}, {%4,%5,%6,%7}, {%8,%9}, {%0,%1,%2,%3};"
        : "+f"(c[0]), "+f"(c[1]), "+f"(c[2]), "+f"(c[3])
        : "r"(a[0]), "r"(a[1]), "r"(a[2]), "r"(a[3]), "r"(b[0]), "r"(b[1]));
}

template<int BM, int BN, int STAGES>
constexpr int gemm_smem_bytes() { return STAGES * (BM + BN) * 40 * 2; }

template<int BM, int BN, int WM, int WN, int STAGES>
__global__ void __launch_bounds__(256) k_mma_gemm(
        const __half* __restrict__ A,
        const __half* __restrict__ B,
        float* __restrict__ C, int M, int N, int K, int n_off,
        const float* __restrict__ att_src, const float* __restrict__ att_dst,
        float* __restrict__ out_s, float* __restrict__ out_d, int nh) {
    constexpr int WT_M = BM / WM;
    constexpr int WT_N = BN / WN;
    constexpr int MF = WT_M / 16;
    constexpr int NF = WT_N / 8;
    constexpr int LDS = 40;
    constexpr int A_LD = BM * 4 / 256;
    constexpr int B_LD = (BN * 4 + 255) / 256;
    constexpr uint32_t ABUF = BM * LDS * 2;
    constexpr uint32_t BBUF = BN * LDS * 2;
    constexpr int PREF = STAGES - 1;

    extern __shared__ char dynsm[];
    __half* Asm = (__half*)dynsm;
    __half* Bsm = Asm + STAGES * BM * LDS;

    int tid = threadIdx.x;
    int w = tid >> 5, lane = tid & 31;
    int g = lane >> 2, t4 = lane & 3;
    int wm = w / WN, wn = w % WN;
    int m0 = blockIdx.y * BM;
    int n0 = blockIdx.x * BN + n_off;
    int wrow = wm * WT_M, wcol = wn * WT_N;
    const int NIT = K / 32;

    int arow = lane & 15;
    int akof = (lane >> 4) << 3;
    int q8 = lane >> 3;
    int brow = ((q8 & 2) ? 8 : 0) + (lane & 7);
    int bkof = (q8 & 1) << 3;
    uint32_t aS = smem_u32(Asm);
    uint32_t bS = smem_u32(Bsm);

    float acc[MF][NF][4];
    #pragma unroll
    for (int i = 0; i < MF; i++)
        #pragma unroll
        for (int j = 0; j < NF; j++)
            #pragma unroll
            for (int q = 0; q < 4; q++) acc[i][j][q] = 0.f;

    auto issue_tile = [&](int it) {
        if (it < NIT) {
            int k0 = it * 32;
            int st = it % STAGES;
            #pragma unroll
            for (int q = 0; q < A_LD; q++) {
                int idx = tid + q * 256;
                int row = idx >> 2, seg = idx & 3;
                int gr = m0 + row;
                int grc = gr < M ? gr : M - 1;
                cp16(aS + st * ABUF + 2u * (row * LDS + seg * 8),
                     A + (size_t)grc * K + k0 + seg * 8, gr < M ? 16 : 0);
            }
            #pragma unroll
            for (int q = 0; q < B_LD; q++) {
                int idx = tid + q * 256;
                if (BN * 4 % 256 == 0 || idx < BN * 4) {
                    int row = idx >> 2, seg = idx & 3;
                    cp16(bS + st * BBUF + 2u * (row * LDS + seg * 8),
                         B + (size_t)(n0 + row) * K + k0 + seg * 8, 16);
                }
            }
        }
        CP_COMMIT();
    };

    #pragma unroll
    for (int p = 0; p < PREF; p++) issue_tile(p);

    for (int it = 0; it < NIT; it++) {
        CP_WAIT(PREF - 1);
        __syncthreads();
        int st = it % STAGES;
        uint32_t aB = aS + st * ABUF;
        uint32_t bB = bS + st * BBUF;
        #pragma unroll
        for (int ks = 0; ks < 32; ks += 16) {
            uint32_t af[MF][4], bf[NF][2];
            #pragma unroll
            for (int mi = 0; mi < MF; mi++)
                ldmatrix_x4(af[mi], aB + 2u * ((wrow + mi * 16 + arow) * LDS + ks + akof));
            #pragma unroll
            for (int nj = 0; nj < NF / 2; nj++) {
                uint32_t tt[4];
                ldmatrix_x4(tt, bB + 2u * ((wcol + nj * 16 + brow) * LDS + ks + bkof));
                bf[2 * nj][0] = tt[0]; bf[2 * nj][1] = tt[1];
                bf[2 * nj + 1][0] = tt[2]; bf[2 * nj + 1][1] = tt[3];
            }
            #pragma unroll
            for (int mi = 0; mi < MF; mi++)
                #pragma unroll
                for (int ni = 0; ni < NF; ni++)
                    mma16816(acc[mi][ni], af[mi], bf[ni]);
        }
        issue_tile(it + PREF);
    }
    CP_WAIT(0);
    __syncthreads();

    // ---- fused attention-coefficient epilogue (single writer per head) ----
    if (att_src) {
        float* s1a = (float*)Asm;
        float* s2a = s1a + BM;
        if (tid < BM) { s1a[tid] = 0.f; s2a[tid] = 0.f; }
        __syncthreads();
        float asr[NF][2], adr[NF][2];
        #pragma unroll
        for (int ni = 0; ni < NF; ni++)
            #pragma unroll
            for (int q = 0; q < 2; q++) {
                int gc = n0 + wcol + ni * 8 + 2 * t4 + q;
                asr[ni][q] = att_src[gc];
                adr[ni][q] = att_dst[gc];
            }
        #pragma unroll
        for (int mi = 0; mi < MF; mi++) {
            #pragma unroll
            for (int half = 0; half < 2; half++) {
                float p1 = 0.f, p2 = 0.f;
                #pragma unroll
                for (int ni = 0; ni < NF; ni++)
                    #pragma unroll
                    for (int q = 0; q < 2; q++) {
                        float v = acc[mi][ni][half * 2 + q];
                        p1 += v * asr[ni][q];
                        p2 += v * adr[ni][q];
                    }
                p1 += __shfl_xor_sync(~0u, p1, 1); p1 += __shfl_xor_sync(~0u, p1, 2);
                p2 += __shfl_xor_sync(~0u, p2, 1); p2 += __shfl_xor_sync(~0u, p2, 2);
                if (t4 == 0) {
                    int r = wrow + mi * 16 + half * 8 + g;
                    atomicAdd(&s1a[r], p1);
                    atomicAdd(&s2a[r], p2);
                }
            }
        }
        __syncthreads();
        int head = n0 / (N / nh);
        if (tid < BM && m0 + tid < M) {
            out_s[(size_t)(m0 + tid) * nh + head] = s1a[tid];
            out_d[(size_t)(m0 + tid) * nh + head] = s2a[tid];
        }
    }

    // ---- C store ----
    #pragma unroll
    for (int mi = 0; mi < MF; mi++) {
        #pragma unroll
        for (int ni = 0; ni < NF; ni++) {
            int r = m0 + wrow + mi * 16 + g;
            int c = n0 + wcol + ni * 8 + 2 * t4;
            if (r < M)     *(float2*)&C[(size_t)r * N + c]       = make_float2(acc[mi][ni][0], acc[mi][ni][1]);
            if (r + 8 < M) *(float2*)&C[(size_t)(r + 8) * N + c] = make_float2(acc[mi][ni][2], acc[mi][ni][3]);
        }
    }
}

// ===== fused layer-1 softmax + agg + bias + ELU for nh heads [h0, h0+nh) =====
__global__ void k_smagg1(const float* __restrict__ b1, int h0, int nh) {
    int d = blockIdx.x;
    int t = threadIdx.x, lane = t & 31, w = t >> 5;
    int jb = d * CAP;
    int je = jb + g_cursor[d];
    __shared__ float s_m[8], s_rd[8];
    __shared__ float sv[SMX * 8];
    __shared__ int   ssrc[32];
    __shared__ float salpha[32 * 8];

    int gh = h0 + w;
    float adst = g_adst1[d * HEADS + gh];
    float m = -1e30f;
    for (int j = jb + lane; j < je; j += 32) {
        int s = g_csrsrc[j];
        float v = g_asrc1[s * HEADS + gh] + adst;
        v = v > 0.f ? v : 0.2f * v;
        int idx = j - jb;
        if (idx < SMX) sv[idx * nh + w] = v;
        m = fmaxf(m, v);
    }
    #pragma unroll
    for (int o = 16; o; o >>= 1) m = fmaxf(m, __shfl_xor_sync(~0u, m, o));
    float den = 0.f;
    for (int j = jb + lane; j < je; j += 32) {
        int idx = j - jb;
        float v;
        if (idx < SMX) v = sv[idx * nh + w];
        else {
            v = g_asrc1[g_csrsrc[j] * HEADS + gh] + adst;
            v = v > 0.f ? v : 0.2f * v;
        }
        float e = expf(v - m);
        if (idx < SMX) sv[idx * nh + w] = e;
        den += e;
    }
    #pragma unroll
    for (int o = 16; o; o >>= 1) den += __shfl_xor_sync(~0u, den, o);
    if (lane == 0) { s_m[w] = m; s_rd[w] = 1.f / (den + 1e-16f); }
    __syncthreads();

    int eh = t / nh, hh = t % nh;
    float rd2 = s_rd[hh], m2 = s_m[hh];
    float adsth = g_adst1[d * HEADS + h0 + hh];
    int lh = t >> 5;
    int fc = h0 * 32 + t;
    const float4* xl = (const float4*)g_xl1;
    float4 acc = make_float4(0.f, 0.f, 0.f, 0.f);

    for (int j0 = jb; j0 < je; j0 += 32) {
        int cnt = min(32, je - j0);
        __syncthreads();
        if (t < cnt) ssrc[t] = g_csrsrc[j0 + t];
        __syncthreads();
        if (eh < cnt) {
            int idx = j0 - jb + eh;
            float e;
            if (idx < SMX) e = sv[idx * nh + hh];
            else {
                float v = g_asrc1[ssrc[eh] * HEADS + h0 + hh] + adsth;
                v = v > 0.f ? v : 0.2f * v;
                e = expf(v - m2);
            }
            salpha[eh * nh + hh] = e * rd2;
        }
        __syncthreads();
        #pragma unroll 2
        for (int jj = 0; jj < cnt; jj++) {
            int s = ssrc[jj];
            float a = salpha[jj * nh + lh];
            float4 xv = xl[(size_t)s * (F1 / 4) + fc];
            acc.x += a * xv.x; acc.y += a * xv.y;
            acc.z += a * xv.z; acc.w += a * xv.w;
        }
    }

    float4 bb = ((const float4*)b1)[fc];
    float v[4];
    v[0] = acc.x + bb.x; v[1] = acc.y + bb.y; v[2] = acc.z + bb.z; v[3] = acc.w + bb.w;
    #pragma unroll
    for (int q = 0; q < 4; q++) v[q] = v[q] > 0.f ? v[q] : expm1f(v[q]);
    __half hi[4], lo[4];
    #pragma unroll
    for (int q = 0; q < 4; q++) {
        hi[q] = __float2half(v[q]);
        lo[q] = __float2half(v[q] - __half2float(hi[q]));
    }
    __half* row = g_h1e + (size_t)d * K2;
    *(uint2*)&row[4 * fc]      = *(uint2*)hi;
    *(uint2*)&row[4 * fc + F1] = *(uint2*)lo;
}

// ===== fused layer-2 softmax + aggregation + bias + LayerNorm =====
__global__ void __launch_bounds__(64) k_smagg2ln(
        const float* __restrict__ b2, const float* __restrict__ gamma,
        const float* __restrict__ beta, float* __restrict__ out) {
    int d = blockIdx.x;
    int t = threadIdx.x, lane = t & 31, w = t >> 5;
    int jb = d * CAP;
    int je = jb + g_cursor[d];
    __shared__ float redm[2], redd[2];
    __shared__ int   ssrc[64];
    __shared__ float salpha[64];

    float adst = g_adst2[d];
    float m = -1e30f;
    for (int j = jb + t; j < je; j += 64) {
        float v = g_asrc2[g_csrsrc[j]] + adst;
        v = v > 0.f ? v : 0.2f * v;
        m = fmaxf(m, v);
    }
    #pragma unroll
    for (int o = 16; o; o >>= 1) m = fmaxf(m, __shfl_xor_sync(~0u, m, o));
    if (lane == 0) redm[w] = m;
    __syncthreads();
    m = fmaxf(redm[0], redm[1]);
    float den = 0.f;
    for (int j = jb + t; j < je; j += 64) {
        float v = g_asrc2[g_csrsrc[j]] + adst;
        v = v > 0.f ? v : 0.2f * v;
        den += expf(v - m);
    }
    #pragma unroll
    for (int o = 16; o; o >>= 1) den += __shfl_xor_sync(~0u, den, o);
    if (lane == 0) redd[w] = den;
    __syncthreads();
    float rd = 1.f / (redd[0] + redd[1] + 1e-16f);

    float acc = 0.f;
    for (int j0 = jb; j0 < je; j0 += 64) {
        int cnt = min(64, je - j0);
        __syncthreads();
        if (t < cnt) {
            int s = g_csrsrc[j0 + t];
            ssrc[t] = s;
            float v = g_asrc2[s] + adst;
            v = v > 0.f ? v : 0.2f * v;
            salpha[t] = expf(v - m) * rd;
        }
        __syncthreads();
        #pragma unroll 2
        for (int jj = 0; jj < cnt; jj++)
            acc += salpha[jj] * g_h2[(size_t)ssrc[jj] * ODIM + t];
    }

    float val = acc + b2[t];
    float s = val;
    #pragma unroll
    for (int o = 16; o; o >>= 1) s += __shfl_xor_sync(~0u, s, o);
    __syncthreads();
    if (lane == 0) redd[w] = s;
    __syncthreads();
    float mu = (redd[0] + redd[1]) * (1.f / 64.f);
    float dv = val - mu;
    float q = dv * dv;
    #pragma unroll
    for (int o = 16; o; o >>= 1) q += __shfl_xor_sync(~0u, q, o);
    __syncthreads();
    if (lane == 0) redm[w] = q;
    __syncthreads();
    float inv = rsqrtf((redm[0] + redm[1]) * (1.f / 64.f) + 1e-5f);
    out[(size_t)d * ODIM + t] = dv * inv * gamma[t] + beta[t];
}

// ================= launch =================
extern "C" void kernel_launch(void* const* d_in, const int* in_sizes, int n_in,
                              void* d_out, int out_size) {
    const float* x     = (const float*)d_in[0];
    const int*   ei    = (const int*)  d_in[1];
    const float* W1    = (const float*)d_in[2];
    const float* as1   = (const float*)d_in[3];
    const float* ad1   = (const float*)d_in[4];
    const float* b1    = (const float*)d_in[5];
    const float* W2    = (const float*)d_in[6];
    const float* as2   = (const float*)d_in[7];
    const float* ad2   = (const float*)d_in[8];
    const float* b2    = (const float*)d_in[9];
    const float* gamma = (const float*)d_in[10];
    const float* beta  = (const float*)d_in[11];
    float* out = (float*)d_out;

    __half *xe, *w1e, *h1e, *w2e;
    float *xl1, *h2, *asrc1, *adst1, *asrc2, *adst2;
    cudaGetSymbolAddress((void**)&xe,    g_xe);
    cudaGetSymbolAddress((void**)&w1e,   g_w1e);
    cudaGetSymbolAddress((void**)&h1e,   g_h1e);
    cudaGetSymbolAddress((void**)&w2e,   g_w2e);
    cudaGetSymbolAddress((void**)&xl1,   g_xl1);
    cudaGetSymbolAddress((void**)&h2,    g_h2);
    cudaGetSymbolAddress((void**)&asrc1, g_asrc1);
    cudaGetSymbolAddress((void**)&adst1, g_adst1);
    cudaGetSymbolAddress((void**)&asrc2, g_asrc2);
    cudaGetSymbolAddress((void**)&adst2, g_adst2);

    constexpr int SM1 = gemm_smem_bytes<128, 128, 4>();   // 81920
    constexpr int SM2 = gemm_smem_bytes<64, 64, 6>();     // 61440
    cudaFuncSetAttribute(k_mma_gemm<128, 128, 2, 4, 4>,
                         cudaFuncAttributeMaxDynamicSharedMemorySize, SM1);
    cudaFuncSetAttribute(k_mma_gemm<64, 64, 2, 4, 6>,
                         cudaFuncAttributeMaxDynamicSharedMemorySize, SM2);

    static cudaStream_t s_side = nullptr;
    static cudaEvent_t  s_ev0 = nullptr, s_evA = nullptr, s_evScat = nullptr, s_ev1 = nullptr;
    if (!s_side) {
        cudaStreamCreateWithFlags(&s_side, cudaStreamNonBlocking);
        cudaEventCreateWithFlags(&s_ev0,   cudaEventDisableTiming);
        cudaEventCreateWithFlags(&s_evA,   cudaEventDisableTiming);
        cudaEventCreateWithFlags(&s_evScat,cudaEventDisableTiming);
        cudaEventCreateWithFlags(&s_ev1,   cudaEventDisableTiming);
    }

    cudaEventRecord(s_ev0, 0);
    cudaStreamWaitEvent(s_side, s_ev0, 0);

    // submission order: cvt1(0), side0(1), scatter(2), GEMM1a(3 -> ncu target)
    k_cvt1<<<(NN * IN_DIM + IN_DIM * F1 + 255) / 256, 256>>>(x, W1);
    k_side0<<<(NN + F1 * ODIM + 255) / 256, 256, 0, s_side>>>(W2);
    k_scatter<<<(ET + 255) / 256, 256, 0, s_side>>>(ei);
    {   // GEMM1a: heads 0-5 (cols 0-767), 474 CTAs
        dim3 g(6, (NN + 127) / 128);
        k_mma_gemm<128, 128, 2, 4, 4><<<g, 256, SM1>>>(
            xe, w1e, xl1, NN, F1, K1, 0, as1, ad1, asrc1, adst1, HEADS);
    }
    cudaEventRecord(s_evScat, s_side);
    cudaEventRecord(s_evA, 0);

    // side stream: smagg1 heads 0-5 (6-head block), overlaps GEMM1b + smagg1b
    cudaStreamWaitEvent(s_side, s_evA, 0);
    k_smagg1<<<NN, 192, 0, s_side>>>(b1, 0, 6);
    cudaEventRecord(s_ev1, s_side);

    {   // GEMM1b: heads 6-7 (cols 768-1023), 158 CTAs ~ 1 wave
        dim3 g(2, (NN + 127) / 128);
        k_mma_gemm<128, 128, 2, 4, 4><<<g, 256, SM1>>>(
            xe, w1e, xl1, NN, F1, K1, 768, as1, ad1, asrc1, adst1, HEADS);
    }
    cudaStreamWaitEvent(0, s_evScat, 0);
    k_smagg1<<<NN, 64>>>(b1, 6, 2);

    cudaStreamWaitEvent(0, s_ev1, 0);
    {   // GEMM2 + fused attn2 (K = 2048)
        dim3 g(1, (NN + 63) / 64);
        k_mma_gemm<64, 64, 2, 4, 6><<<g, 256, SM2>>>(
            h1e, w2e, h2, NN, ODIM, K2, 0, as2, ad2, asrc2, adst2, 1);
    }
    k_smagg2ln<<<NN, 64>>>(b2, gamma, beta, out);
}

// round 17
// speedup vs baseline: 1.6674x; 1.2507x over previous
#include <cuda_runtime.h>
#include <cuda_fp16.h>
#include <math.h>
#include <stdint.h>

#define NN      10000
#define NE      160000
#define ET      170000
#define IN_DIM  256
#define HID     128
#define HEADS   8
#define F1      1024
#define ODIM    64

#define K1      IN_DIM          // 256 : GEMM1 K (plain fp16)
#define K2      F1              // 1024: GEMM2 K (plain fp16)
#define SMX     96
#define CAP     128             // bucket capacity per dst

// ================= scratch =================
__device__ float g_xl1  [NN * F1];
__device__ float g_asrc1[NN * HEADS];
__device__ float g_adst1[NN * HEADS];
__device__ float g_h2   [NN * ODIM];
__device__ float g_asrc2[NN];
__device__ float g_adst2[NN];
__device__ int g_cursor[NN];
__device__ int g_csrsrc[NN * CAP];
__device__ __half g_xe  [NN * K1];
__device__ __half g_w1e [F1 * K1];
__device__ __half g_h1e [NN * K2];
__device__ __half g_w2e [ODIM * K2];

__device__ __forceinline__ uint32_t smem_u32(const void* p) {
    uint32_t a;
    asm("{ .reg .u64 t; cvta.to.shared.u64 t, %1; cvt.u32.u64 %0, t; }" : "=r"(a) : "l"(p));
    return a;
}
__device__ __forceinline__ void ldmatrix_x4(uint32_t* r, uint32_t addr) {
    asm volatile("ldmatrix.sync.aligned.m8n8.x4.shared.b16 {%0,%1,%2,%3}, [%4];"
        : "=r"(r[0]), "=r"(r[1]), "=r"(r[2]), "=r"(r[3]) : "r"(addr));
}
__device__ __forceinline__ void cp16(uint32_t dst, const void* src, int bytes) {
    asm volatile("cp.async.cg.shared.global [%0], [%1], 16, %2;"
        :: "r"(dst), "l"(src), "r"(bytes));
}
#define CP_COMMIT() asm volatile("cp.async.commit_group;" ::: "memory")
#define CP_WAIT(n)  asm volatile("cp.async.wait_group %0;" :: "n"(n) : "memory")

// ================= side0: zero cursor + cvt_w2 =================
__global__ void k_side0(const float* __restrict__ W2) {
    int i = blockIdx.x * blockDim.x + threadIdx.x;
    if (i < NN) g_cursor[i] = 0;
    int j = i - NN;
    if (j >= 0 && j < F1 * ODIM) {
        int k = j >> 6, n = j & (ODIM - 1);
        g_w2e[(size_t)n * K2 + k] = __float2half(W2[j]);
    }
}

// ================= bucket scatter =================
__global__ void k_scatter(const int* __restrict__ ei) {
    int e = blockIdx.x * blockDim.x + threadIdx.x;
    if (e >= ET) return;
    int s, d;
    if (e < NE) { s = ei[e]; d = ei[NE + e]; }
    else        { s = e - NE; d = e - NE; }
    int pos = atomicAdd(&g_cursor[d], 1);
    g_csrsrc[d * CAP + pos] = s;
}

// ================= cvt: x and W1 to fp16 =================
__global__ void k_cvt1(const float* __restrict__ x, const float* __restrict__ W1) {
    int i = blockIdx.x * blockDim.x + threadIdx.x;
    if (i < NN * IN_DIM) {
        g_xe[i] = __float2half(x[i]);
        return;
    }
    int j = i - NN * IN_DIM;
    if (j < IN_DIM * F1) {
        int k = j >> 10, n = j & (F1 - 1);
        g_w1e[(size_t)n * K1 + k] = __float2half(W1[j]);
    }
}

// ================= cp.async-pipelined fp16 mma GEMM (dynamic smem) =================
__device__ __forceinline__ void mma16816(float* c, const uint32_t* a, const uint32_t* b) {
    asm volatile(
        "mma.sync.aligned.m16n8k16.row.col.f32.f16.f16.f32 "
        "{%0,%1,%2,%3}, {%4,%5,%6,%7}, {%8,%9}, {%0,%1,%2,%3};"
        : "+f"(c[0]), "+f"(c[1]), "+f"(c[2]), "+f"(c[3])
        : "r"(a[0]), "r"(a[1]), "r"(a[2]), "r"(a[3]), "r"(b[0]), "r"(b[1]));
}

template<int BM, int BN, int STAGES>
constexpr int gemm_smem_bytes() { return STAGES * (BM + BN) * 40 * 2; }

template<int BM, int BN, int WM, int WN, int STAGES>
__global__ void __launch_bounds__(256) k_mma_gemm(
        const __half* __restrict__ A,
        const __half* __restrict__ B,
        float* __restrict__ C, int M, int N, int K, int n_off,
        const float* __restrict__ att_src, const float* __restrict__ att_dst,
        float* __restrict__ out_s, float* __restrict__ out_d, int nh) {
    constexpr int WT_M = BM / WM;
    constexpr int WT_N = BN / WN;
    constexpr int MF = WT_M / 16;
    constexpr int NF = WT_N / 8;
    constexpr int LDS = 40;
    constexpr int A_LD = BM * 4 / 256;
    constexpr int B_LD = (BN * 4 + 255) / 256;
    constexpr uint32_t ABUF = BM * LDS * 2;
    constexpr uint32_t BBUF = BN * LDS * 2;
    constexpr int PREF = STAGES - 1;

    extern __shared__ char dynsm[];
    __half* Asm = (__half*)dynsm;
    __half* Bsm = Asm + STAGES * BM * LDS;

    int tid = threadIdx.x;
    int w = tid >> 5, lane = tid & 31;
    int g = lane >> 2, t4 = lane & 3;
    int wm = w / WN, wn = w % WN;
    int m0 = blockIdx.y * BM;
    int n0 = blockIdx.x * BN + n_off;
    int wrow = wm * WT_M, wcol = wn * WT_N;
    const int NIT = K / 32;

    int arow = lane & 15;
    int akof = (lane >> 4) << 3;
    int q8 = lane >> 3;
    int brow = ((q8 & 2) ? 8 : 0) + (lane & 7);
    int bkof = (q8 & 1) << 3;
    uint32_t aS = smem_u32(Asm);
    uint32_t bS = smem_u32(Bsm);

    float acc[MF][NF][4];
    #pragma unroll
    for (int i = 0; i < MF; i++)
        #pragma unroll
        for (int j = 0; j < NF; j++)
            #pragma unroll
            for (int q = 0; q < 4; q++) acc[i][j][q] = 0.f;

    auto issue_tile = [&](int it) {
        if (it < NIT) {
            int k0 = it * 32;
            int st = it % STAGES;
            #pragma unroll
            for (int q = 0; q < A_LD; q++) {
                int idx = tid + q * 256;
                int row = idx >> 2, seg = idx & 3;
                int gr = m0 + row;
                int grc = gr < M ? gr : M - 1;
                cp16(aS + st * ABUF + 2u * (row * LDS + seg * 8),
                     A + (size_t)grc * K + k0 + seg * 8, gr < M ? 16 : 0);
            }
            #pragma unroll
            for (int q = 0; q < B_LD; q++) {
                int idx = tid + q * 256;
                if (BN * 4 % 256 == 0 || idx < BN * 4) {
                    int row = idx >> 2, seg = idx & 3;
                    cp16(bS + st * BBUF + 2u * (row * LDS + seg * 8),
                         B + (size_t)(n0 + row) * K + k0 + seg * 8, 16);
                }
            }
        }
        CP_COMMIT();
    };

    #pragma unroll
    for (int p = 0; p < PREF; p++) issue_tile(p);

    for (int it = 0; it < NIT; it++) {
        CP_WAIT(PREF - 1);
        __syncthreads();
        int st = it % STAGES;
        uint32_t aB = aS + st * ABUF;
        uint32_t bB = bS + st * BBUF;
        #pragma unroll
        for (int ks = 0; ks < 32; ks += 16) {
            uint32_t af[MF][4], bf[NF][2];
            #pragma unroll
            for (int mi = 0; mi < MF; mi++)
                ldmatrix_x4(af[mi], aB + 2u * ((wrow + mi * 16 + arow) * LDS + ks + akof));
            #pragma unroll
            for (int nj = 0; nj < NF / 2; nj++) {
                uint32_t tt[4];
                ldmatrix_x4(tt, bB + 2u * ((wcol + nj * 16 + brow) * LDS + ks + bkof));
                bf[2 * nj][0] = tt[0]; bf[2 * nj][1] = tt[1];
                bf[2 * nj + 1][0] = tt[2]; bf[2 * nj + 1][1] = tt[3];
            }
            #pragma unroll
            for (int mi = 0; mi < MF; mi++)
                #pragma unroll
                for (int ni = 0; ni < NF; ni++)
                    mma16816(acc[mi][ni], af[mi], bf[ni]);
        }
        issue_tile(it + PREF);
    }
    CP_WAIT(0);
    __syncthreads();

    // ---- fused attention-coefficient epilogue (single writer per head) ----
    if (att_src) {
        float* s1a = (float*)Asm;
        float* s2a = s1a + BM;
        if (tid < BM) { s1a[tid] = 0.f; s2a[tid] = 0.f; }
        __syncthreads();
        float asr[NF][2], adr[NF][2];
        #pragma unroll
        for (int ni = 0; ni < NF; ni++)
            #pragma unroll
            for (int q = 0; q < 2; q++) {
                int gc = n0 + wcol + ni * 8 + 2 * t4 + q;
                asr[ni][q] = att_src[gc];
                adr[ni][q] = att_dst[gc];
            }
        #pragma unroll
        for (int mi = 0; mi < MF; mi++) {
            #pragma unroll
            for (int half = 0; half < 2; half++) {
                float p1 = 0.f, p2 = 0.f;
                #pragma unroll
                for (int ni = 0; ni < NF; ni++)
                    #pragma unroll
                    for (int q = 0; q < 2; q++) {
                        float v = acc[mi][ni][half * 2 + q];
                        p1 += v * asr[ni][q];
                        p2 += v * adr[ni][q];
                    }
                p1 += __shfl_xor_sync(~0u, p1, 1); p1 += __shfl_xor_sync(~0u, p1, 2);
                p2 += __shfl_xor_sync(~0u, p2, 1); p2 += __shfl_xor_sync(~0u, p2, 2);
                if (t4 == 0) {
                    int r = wrow + mi * 16 + half * 8 + g;
                    atomicAdd(&s1a[r], p1);
                    atomicAdd(&s2a[r], p2);
                }
            }
        }
        __syncthreads();
        int head = n0 / (N / nh);
        if (tid < BM && m0 + tid < M) {
            out_s[(size_t)(m0 + tid) * nh + head] = s1a[tid];
            out_d[(size_t)(m0 + tid) * nh + head] = s2a[tid];
        }
    }

    // ---- C store ----
    #pragma unroll
    for (int mi = 0; mi < MF; mi++) {
        #pragma unroll
        for (int ni = 0; ni < NF; ni++) {
            int r = m0 + wrow + mi * 16 + g;
            int c = n0 + wcol + ni * 8 + 2 * t4;
            if (r < M)     *(float2*)&C[(size_t)r * N + c]       = make_float2(acc[mi][ni][0], acc[mi][ni][1]);
            if (r + 8 < M) *(float2*)&C[(size_t)(r + 8) * N + c] = make_float2(acc[mi][ni][2], acc[mi][ni][3]);
        }
    }
}

// ===== fused layer-1 softmax + agg + bias + ELU for nh heads [h0, h0+nh) =====
__global__ void k_smagg1(const float* __restrict__ b1, int h0, int nh) {
    int d = blockIdx.x;
    int t = threadIdx.x, lane = t & 31, w = t >> 5;
    int jb = d * CAP;
    int je = jb + g_cursor[d];
    __shared__ float s_m[8], s_rd[8];
    __shared__ float sv[SMX * 8];
    __shared__ int   ssrc[32];
    __shared__ float salpha[32 * 8];

    int gh = h0 + w;
    float adst = g_adst1[d * HEADS + gh];
    float m = -1e30f;
    for (int j = jb + lane; j < je; j += 32) {
        int s = g_csrsrc[j];
        float v = g_asrc1[s * HEADS + gh] + adst;
        v = v > 0.f ? v : 0.2f * v;
        int idx = j - jb;
        if (idx < SMX) sv[idx * nh + w] = v;
        m = fmaxf(m, v);
    }
    #pragma unroll
    for (int o = 16; o; o >>= 1) m = fmaxf(m, __shfl_xor_sync(~0u, m, o));
    float den = 0.f;
    for (int j = jb + lane; j < je; j += 32) {
        int idx = j - jb;
        float v;
        if (idx < SMX) v = sv[idx * nh + w];
        else {
            v = g_asrc1[g_csrsrc[j] * HEADS + gh] + adst;
            v = v > 0.f ? v : 0.2f * v;
        }
        float e = expf(v - m);
        if (idx < SMX) sv[idx * nh + w] = e;
        den += e;
    }
    #pragma unroll
    for (int o = 16; o; o >>= 1) den += __shfl_xor_sync(~0u, den, o);
    if (lane == 0) { s_m[w] = m; s_rd[w] = 1.f / (den + 1e-16f); }
    __syncthreads();

    int eh = t / nh, hh = t % nh;
    float rd2 = s_rd[hh], m2 = s_m[hh];
    float adsth = g_adst1[d * HEADS + h0 + hh];
    int lh = t >> 5;
    int fc = h0 * 32 + t;                  // global float4 column
    const float4* xl = (const float4*)g_xl1;
    float4 acc = make_float4(0.f, 0.f, 0.f, 0.f);

    for (int j0 = jb; j0 < je; j0 += 32) {
        int cnt = min(32, je - j0);
        __syncthreads();
        if (t < cnt) ssrc[t] = g_csrsrc[j0 + t];
        __syncthreads();
        if (eh < cnt) {
            int idx = j0 - jb + eh;
            float e;
            if (idx < SMX) e = sv[idx * nh + hh];
            else {
                float v = g_asrc1[ssrc[eh] * HEADS + h0 + hh] + adsth;
                v = v > 0.f ? v : 0.2f * v;
                e = expf(v - m2);
            }
            salpha[eh * nh + hh] = e * rd2;
        }
        __syncthreads();
        #pragma unroll 2
        for (int jj = 0; jj < cnt; jj++) {
            int s = ssrc[jj];
            float a = salpha[jj * nh + lh];
            float4 xv = xl[(size_t)s * (F1 / 4) + fc];
            acc.x += a * xv.x; acc.y += a * xv.y;
            acc.z += a * xv.z; acc.w += a * xv.w;
        }
    }

    float4 bb = ((const float4*)b1)[fc];
    float v[4];
    v[0] = acc.x + bb.x; v[1] = acc.y + bb.y; v[2] = acc.z + bb.z; v[3] = acc.w + bb.w;
    #pragma unroll
    for (int q = 0; q < 4; q++) v[q] = v[q] > 0.f ? v[q] : expm1f(v[q]);
    __half hv[4];
    #pragma unroll
    for (int q = 0; q < 4; q++) hv[q] = __float2half(v[q]);
    *(uint2*)&g_h1e[(size_t)d * K2 + 4 * fc] = *(uint2*)hv;
}

// ===== fused layer-2 softmax + aggregation + bias + LayerNorm =====
__global__ void __launch_bounds__(64) k_smagg2ln(
        const float* __restrict__ b2, const float* __restrict__ gamma,
        const float* __restrict__ beta, float* __restrict__ out) {
    int d = blockIdx.x;
    int t = threadIdx.x, lane = t & 31, w = t >> 5;
    int jb = d * CAP;
    int je = jb + g_cursor[d];
    __shared__ float redm[2], redd[2];
    __shared__ int   ssrc[64];
    __shared__ float salpha[64];

    float adst = g_adst2[d];
    float m = -1e30f;
    for (int j = jb + t; j < je; j += 64) {
        float v = g_asrc2[g_csrsrc[j]] + adst;
        v = v > 0.f ? v : 0.2f * v;
        m = fmaxf(m, v);
    }
    #pragma unroll
    for (int o = 16; o; o >>= 1) m = fmaxf(m, __shfl_xor_sync(~0u, m, o));
    if (lane == 0) redm[w] = m;
    __syncthreads();
    m = fmaxf(redm[0], redm[1]);
    float den = 0.f;
    for (int j = jb + t; j < je; j += 64) {
        float v = g_asrc2[g_csrsrc[j]] + adst;
        v = v > 0.f ? v : 0.2f * v;
        den += expf(v - m);
    }
    #pragma unroll
    for (int o = 16; o; o >>= 1) den += __shfl_xor_sync(~0u, den, o);
    if (lane == 0) redd[w] = den;
    __syncthreads();
    float rd = 1.f / (redd[0] + redd[1] + 1e-16f);

    float acc = 0.f;
    for (int j0 = jb; j0 < je; j0 += 64) {
        int cnt = min(64, je - j0);
        __syncthreads();
        if (t < cnt) {
            int s = g_csrsrc[j0 + t];
            ssrc[t] = s;
            float v = g_asrc2[s] + adst;
            v = v > 0.f ? v : 0.2f * v;
            salpha[t] = expf(v - m) * rd;
        }
        __syncthreads();
        #pragma unroll 2
        for (int jj = 0; jj < cnt; jj++)
            acc += salpha[jj] * g_h2[(size_t)ssrc[jj] * ODIM + t];
    }

    float val = acc + b2[t];
    float s = val;
    #pragma unroll
    for (int o = 16; o; o >>= 1) s += __shfl_xor_sync(~0u, s, o);
    __syncthreads();
    if (lane == 0) redd[w] = s;
    __syncthreads();
    float mu = (redd[0] + redd[1]) * (1.f / 64.f);
    float dv = val - mu;
    float q = dv * dv;
    #pragma unroll
    for (int o = 16; o; o >>= 1) q += __shfl_xor_sync(~0u, q, o);
    __syncthreads();
    if (lane == 0) redm[w] = q;
    __syncthreads();
    float inv = rsqrtf((redm[0] + redm[1]) * (1.f / 64.f) + 1e-5f);
    out[(size_t)d * ODIM + t] = dv * inv * gamma[t] + beta[t];
}

// ================= launch =================
extern "C" void kernel_launch(void* const* d_in, const int* in_sizes, int n_in,
                              void* d_out, int out_size) {
    const float* x     = (const float*)d_in[0];
    const int*   ei    = (const int*)  d_in[1];
    const float* W1    = (const float*)d_in[2];
    const float* as1   = (const float*)d_in[3];
    const float* ad1   = (const float*)d_in[4];
    const float* b1    = (const float*)d_in[5];
    const float* W2    = (const float*)d_in[6];
    const float* as2   = (const float*)d_in[7];
    const float* ad2   = (const float*)d_in[8];
    const float* b2    = (const float*)d_in[9];
    const float* gamma = (const float*)d_in[10];
    const float* beta  = (const float*)d_in[11];
    float* out = (float*)d_out;

    __half *xe, *w1e, *h1e, *w2e;
    float *xl1, *h2, *asrc1, *adst1, *asrc2, *adst2;
    cudaGetSymbolAddress((void**)&xe,    g_xe);
    cudaGetSymbolAddress((void**)&w1e,   g_w1e);
    cudaGetSymbolAddress((void**)&h1e,   g_h1e);
    cudaGetSymbolAddress((void**)&w2e,   g_w2e);
    cudaGetSymbolAddress((void**)&xl1,   g_xl1);
    cudaGetSymbolAddress((void**)&h2,    g_h2);
    cudaGetSymbolAddress((void**)&asrc1, g_asrc1);
    cudaGetSymbolAddress((void**)&adst1, g_adst1);
    cudaGetSymbolAddress((void**)&asrc2, g_asrc2);
    cudaGetSymbolAddress((void**)&adst2, g_adst2);

    constexpr int SM1 = gemm_smem_bytes<128, 128, 4>();   // 81920
    constexpr int SM2 = gemm_smem_bytes<64, 64, 6>();     // 61440
    cudaFuncSetAttribute(k_mma_gemm<128, 128, 2, 4, 4>,
                         cudaFuncAttributeMaxDynamicSharedMemorySize, SM1);
    cudaFuncSetAttribute(k_mma_gemm<64, 64, 2, 4, 6>,
                         cudaFuncAttributeMaxDynamicSharedMemorySize, SM2);

    static cudaStream_t s_side = nullptr;
    static cudaEvent_t  s_ev0 = nullptr, s_evA = nullptr, s_evScat = nullptr, s_ev1 = nullptr;
    if (!s_side) {
        cudaStreamCreateWithFlags(&s_side, cudaStreamNonBlocking);
        cudaEventCreateWithFlags(&s_ev0,   cudaEventDisableTiming);
        cudaEventCreateWithFlags(&s_evA,   cudaEventDisableTiming);
        cudaEventCreateWithFlags(&s_evScat,cudaEventDisableTiming);
        cudaEventCreateWithFlags(&s_ev1,   cudaEventDisableTiming);
    }

    cudaEventRecord(s_ev0, 0);
    cudaStreamWaitEvent(s_side, s_ev0, 0);

    // submission order: cvt1(0), side0(1), scatter(2), GEMM1a(3 -> ncu target)
    k_cvt1<<<(NN * IN_DIM + IN_DIM * F1 + 255) / 256, 256>>>(x, W1);
    k_side0<<<(NN + F1 * ODIM + 255) / 256, 256, 0, s_side>>>(W2);
    k_scatter<<<(ET + 255) / 256, 256, 0, s_side>>>(ei);
    {   // GEMM1a: heads 0-5 (cols 0-767), 474 CTAs, K=256
        dim3 g(6, (NN + 127) / 128);
        k_mma_gemm<128, 128, 2, 4, 4><<<g, 256, SM1>>>(
            xe, w1e, xl1, NN, F1, K1, 0, as1, ad1, asrc1, adst1, HEADS);
    }
    cudaEventRecord(s_evScat, s_side);
    cudaEventRecord(s_evA, 0);

    // side stream: smagg1 heads 0-5, overlaps GEMM1b + smagg1b
    cudaStreamWaitEvent(s_side, s_evA, 0);
    k_smagg1<<<NN, 192, 0, s_side>>>(b1, 0, 6);
    cudaEventRecord(s_ev1, s_side);

    {   // GEMM1b: heads 6-7 (cols 768-1023), 158 CTAs ~ 1 wave
        dim3 g(2, (NN + 127) / 128);
        k_mma_gemm<128, 128, 2, 4, 4><<<g, 256, SM1>>>(
            xe, w1e, xl1, NN, F1, K1, 768, as1, ad1, asrc1, adst1, HEADS);
    }
    cudaStreamWaitEvent(0, s_evScat, 0);
    k_smagg1<<<NN, 64>>>(b1, 6, 2);

    cudaStreamWaitEvent(0, s_ev1, 0);
    {   // GEMM2 + fused attn2 (K = 1024)
        dim3 g(1, (NN + 63) / 64);
        k_mma_gemm<64, 64, 2, 4, 6><<<g, 256, SM2>>>(
            h1e, w2e, h2, NN, ODIM, K2, 0, as2, ad2, asrc2, adst2, 1);
    }
    k_smagg2ln<<<NN, 64>>>(b2, gamma, beta, out);
}